// round 1
// baseline (speedup 1.0000x reference)
#include <cuda_runtime.h>
#include <math.h>

// ---------------------------------------------------------------------------
// AttentionLayer: y = softmax((XqW^T+b)(XkW^T+b)^T / sqrt(D)) (XvW^T+b)
// N=4, S=T=2048, D=1024, fp32.
// Round 0 baseline: tiled fp32 SGEMM (128x128x8, 8x8 per thread) + row softmax.
// ---------------------------------------------------------------------------

#define BM 128
#define BN 128
#define BK 8
#define TPAD 132   // 128 + 4 pad: kills 2-way LDS conflicts, keeps 16B alignment

static const int NB = 4;
static const int SEQ = 2048;
static const int DIM = 1024;

// Scratch (no allocations allowed -> __device__ globals)
__device__ float g_q[(long long)NB * SEQ * DIM];
__device__ float g_k[(long long)NB * SEQ * DIM];
__device__ float g_v[(long long)NB * SEQ * DIM];
__device__ float g_s[(long long)NB * SEQ * SEQ];

// BT = true : B is [N x K] row-major (K-contiguous), computes A * B^T   (NT)
// BT = false: B is [K x N] row-major (N-contiguous), computes A * B     (NN)
template <bool BT>
__global__ __launch_bounds__(256) void sgemm128(
    const float* __restrict__ A, const float* __restrict__ B, float* __restrict__ C,
    int M, int N, int K, int lda, int ldb, int ldc,
    long long sA, long long sB, long long sC,
    float alpha, const float* __restrict__ bias)
{
    const int z = blockIdx.z;
    A += (long long)z * sA;
    B += (long long)z * sB;
    C += (long long)z * sC;

    const int m0 = blockIdx.y * BM;
    const int n0 = blockIdx.x * BN;
    const int tid = threadIdx.x;
    const int tx = tid & 15;   // 16 thread cols
    const int ty = tid >> 4;   // 16 thread rows

    __shared__ float As[BK][TPAD];
    __shared__ float Bs[BK][TPAD];

    float acc[8][8];
#pragma unroll
    for (int i = 0; i < 8; i++)
#pragma unroll
        for (int j = 0; j < 8; j++) acc[i][j] = 0.0f;

    // A tile loader mapping: 128 rows x 8 cols, 2 float4 per row
    const int arow = tid >> 1;
    const int ac4  = (tid & 1) * 4;
    // B tile loader mapping
    const int brow_t = tid >> 1;        // BT: 128 rows x 8 cols
    const int bc4_t  = (tid & 1) * 4;
    const int brow_n = tid >> 5;        // NN: 8 rows x 128 cols
    const int bc4_n  = (tid & 31) * 4;

    for (int k0 = 0; k0 < K; k0 += BK) {
        // Load A tile (A is always [M x K] row-major), transpose into As[k][m]
        {
            const float4 av = *(const float4*)&A[(long long)(m0 + arow) * lda + k0 + ac4];
            As[ac4 + 0][arow] = av.x;
            As[ac4 + 1][arow] = av.y;
            As[ac4 + 2][arow] = av.z;
            As[ac4 + 3][arow] = av.w;
        }
        if (BT) {
            const float4 bv = *(const float4*)&B[(long long)(n0 + brow_t) * ldb + k0 + bc4_t];
            Bs[bc4_t + 0][brow_t] = bv.x;
            Bs[bc4_t + 1][brow_t] = bv.y;
            Bs[bc4_t + 2][brow_t] = bv.z;
            Bs[bc4_t + 3][brow_t] = bv.w;
        } else {
            const float4 bv = *(const float4*)&B[(long long)(k0 + brow_n) * ldb + n0 + bc4_n];
            *(float4*)&Bs[brow_n][bc4_n] = bv;
        }
        __syncthreads();

#pragma unroll
        for (int k = 0; k < BK; k++) {
            float a[8], b[8];
            *(float4*)&a[0] = *(const float4*)&As[k][ty * 8];
            *(float4*)&a[4] = *(const float4*)&As[k][ty * 8 + 4];
            *(float4*)&b[0] = *(const float4*)&Bs[k][tx * 8];
            *(float4*)&b[4] = *(const float4*)&Bs[k][tx * 8 + 4];
#pragma unroll
            for (int i = 0; i < 8; i++)
#pragma unroll
                for (int j = 0; j < 8; j++)
                    acc[i][j] = fmaf(a[i], b[j], acc[i][j]);
        }
        __syncthreads();
    }

    // Epilogue: C = alpha*acc (+ bias)
#pragma unroll
    for (int i = 0; i < 8; i++) {
        const long long m = m0 + ty * 8 + i;
#pragma unroll
        for (int j = 0; j < 8; j += 4) {
            const int n = n0 + tx * 8 + j;
            float4 o;
            o.x = alpha * acc[i][j + 0];
            o.y = alpha * acc[i][j + 1];
            o.z = alpha * acc[i][j + 2];
            o.w = alpha * acc[i][j + 3];
            if (bias) {
                o.x += bias[n + 0];
                o.y += bias[n + 1];
                o.z += bias[n + 2];
                o.w += bias[n + 3];
            }
            *(float4*)&C[m * ldc + n] = o;
        }
    }
}

// Row softmax over T=2048 elements, one block (256 threads) per row.
__global__ __launch_bounds__(256) void softmax_rows(float* __restrict__ S, int T)
{
    float* p = S + (long long)blockIdx.x * T;
    const int tid = threadIdx.x;
    const int lane = tid & 31;
    const int wid = tid >> 5;

    float v[8];
    *(float4*)&v[0] = *(const float4*)&p[tid * 8];
    *(float4*)&v[4] = *(const float4*)&p[tid * 8 + 4];

    __shared__ float red[8];

    // max reduce
    float m = v[0];
#pragma unroll
    for (int i = 1; i < 8; i++) m = fmaxf(m, v[i]);
#pragma unroll
    for (int o = 16; o > 0; o >>= 1) m = fmaxf(m, __shfl_xor_sync(0xffffffffu, m, o));
    if (lane == 0) red[wid] = m;
    __syncthreads();
    m = red[0];
#pragma unroll
    for (int i = 1; i < 8; i++) m = fmaxf(m, red[i]);
    __syncthreads();

    // exp + sum reduce
    float s = 0.0f;
#pragma unroll
    for (int i = 0; i < 8; i++) {
        v[i] = expf(v[i] - m);
        s += v[i];
    }
#pragma unroll
    for (int o = 16; o > 0; o >>= 1) s += __shfl_xor_sync(0xffffffffu, s, o);
    if (lane == 0) red[wid] = s;
    __syncthreads();
    s = 0.0f;
#pragma unroll
    for (int i = 0; i < 8; i++) s += red[i];

    const float inv = 1.0f / s;
#pragma unroll
    for (int i = 0; i < 8; i++) v[i] *= inv;
    *(float4*)&p[tid * 8] = *(const float4*)&v[0];
    *(float4*)&p[tid * 8 + 4] = *(const float4*)&v[4];
}

extern "C" void kernel_launch(void* const* d_in, const int* in_sizes, int n_in,
                              void* d_out, int out_size)
{
    const float* q_in = (const float*)d_in[0];
    const float* k_in = (const float*)d_in[1];
    const float* v_in = (const float*)d_in[2];
    const float* W    = (const float*)d_in[3];
    const float* bias = (const float*)d_in[4];
    float* out = (float*)d_out;

    float *gq, *gk, *gv, *gs;
    cudaGetSymbolAddress((void**)&gq, g_q);
    cudaGetSymbolAddress((void**)&gk, g_k);
    cudaGetSymbolAddress((void**)&gv, g_v);
    cudaGetSymbolAddress((void**)&gs, g_s);

    const dim3 blk(256);

    // 1) Projections: [NB*SEQ, DIM] = X @ W^T + b   (NT, M=8192, N=K=1024)
    const dim3 gproj(DIM / BN, (NB * SEQ) / BM, 1);
    sgemm128<true><<<gproj, blk>>>(q_in, W, gq, NB * SEQ, DIM, DIM, DIM, DIM, DIM,
                                   0, 0, 0, 1.0f, bias);
    sgemm128<true><<<gproj, blk>>>(k_in, W, gk, NB * SEQ, DIM, DIM, DIM, DIM, DIM,
                                   0, 0, 0, 1.0f, bias);
    sgemm128<true><<<gproj, blk>>>(v_in, W, gv, NB * SEQ, DIM, DIM, DIM, DIM, DIM,
                                   0, 0, 0, 1.0f, bias);

    // 2) Scores: S[n] = (q[n] @ k[n]^T) / sqrt(D)   (NT, batched over NB)
    const float scale = 1.0f / sqrtf((float)DIM);   // 1/32
    const dim3 gsc(SEQ / BN, SEQ / BM, NB);
    sgemm128<true><<<gsc, blk>>>(gq, gk, gs, SEQ, SEQ, DIM, DIM, DIM, SEQ,
                                 (long long)SEQ * DIM, (long long)SEQ * DIM,
                                 (long long)SEQ * SEQ, scale, nullptr);

    // 3) Softmax over T (in place)
    softmax_rows<<<NB * SEQ, 256>>>(gs, SEQ);

    // 4) y[n] = P[n] @ v[n]   (NN, batched over NB)
    const dim3 gpv(DIM / BN, SEQ / BM, NB);
    sgemm128<false><<<gpv, blk>>>(gs, gv, out, SEQ, DIM, SEQ, SEQ, DIM, DIM,
                                  (long long)SEQ * SEQ, (long long)SEQ * DIM,
                                  (long long)SEQ * DIM, 1.0f, nullptr);
}

// round 5
// speedup vs baseline: 2.0674x; 2.0674x over previous
#include <cuda_runtime.h>
#include <cuda_bf16.h>
#include <stdint.h>
#include <math.h>

// ============================================================================
// AttentionLayer via mma.sync (HMMA) bf16 split (hi/lo) GEMMs, fp32 accum.
//   y = softmax((XqW^T+b)(XkW^T+b)^T / 32) (XvW^T+b)
// N=4, S=T=2048, D=1024.
// NOTE: harness PTX target is plain sm_103 (no 'a') -> tcgen05 unavailable;
// mma.sync.m16n8k16.bf16 is the fastest legal tensor path.
// ============================================================================

#define NBATCH 4
#define SEQ    2048
#define DIM    1024

#define STAGES 3
#define PRE    2
#define BK     32
#define ROWB   80                 // 32 bf16 = 64B + 16B pad -> conflict-free LDSM
#define STAGEB (128 * ROWB)       // 10240 B per operand stage
#define SMEM_DYN (STAGES * 2 * STAGEB)   // 61440

// ------------------------- scratch (__device__ globals) ---------------------
#define ND ((long long)NBATCH * SEQ * DIM)   // 8,388,608
#define NS ((long long)NBATCH * SEQ * SEQ)   // 16,777,216

__device__ __align__(256) __nv_bfloat16 g_xq_hi[ND], g_xq_lo[ND];
__device__ __align__(256) __nv_bfloat16 g_xk_hi[ND], g_xk_lo[ND];
__device__ __align__(256) __nv_bfloat16 g_xv_hi[ND], g_xv_lo[ND];
__device__ __align__(256) __nv_bfloat16 g_W_hi[DIM * DIM], g_W_lo[DIM * DIM];
__device__ __align__(256) __nv_bfloat16 g_q_hi[ND], g_q_lo[ND];
__device__ __align__(256) __nv_bfloat16 g_k_hi[ND], g_k_lo[ND];
__device__ __align__(256) __nv_bfloat16 g_vT_hi[ND], g_vT_lo[ND];
__device__ __align__(256) float         g_s[NS];
__device__ __align__(256) __nv_bfloat16 g_p_hi[NS], g_p_lo[NS];

// ------------------------------ PTX helpers ---------------------------------
__device__ __forceinline__ uint32_t s2u(const void* p) {
    uint32_t a;
    asm("{ .reg .u64 t; cvta.to.shared.u64 t, %1; cvt.u32.u64 %0, t; }"
        : "=r"(a) : "l"(p));
    return a;
}
__device__ __forceinline__ void cp16(uint32_t s, const void* g) {
    asm volatile("cp.async.cg.shared.global [%0], [%1], 16;" :: "r"(s), "l"(g) : "memory");
}
__device__ __forceinline__ void cp_commit() {
    asm volatile("cp.async.commit_group;" ::: "memory");
}
template <int N> __device__ __forceinline__ void cp_wait() {
    asm volatile("cp.async.wait_group %0;" :: "n"(N) : "memory");
}
__device__ __forceinline__ void ldsm4(uint32_t* r, uint32_t a) {
    asm volatile("ldmatrix.sync.aligned.m8n8.x4.shared.b16 {%0,%1,%2,%3}, [%4];"
                 : "=r"(r[0]), "=r"(r[1]), "=r"(r[2]), "=r"(r[3]) : "r"(a));
}
__device__ __forceinline__ void mma16816(float* c, const uint32_t* a,
                                         uint32_t b0, uint32_t b1) {
    asm volatile(
        "mma.sync.aligned.m16n8k16.row.col.f32.bf16.bf16.f32 "
        "{%0,%1,%2,%3},{%4,%5,%6,%7},{%8,%9},{%0,%1,%2,%3};"
        : "+f"(c[0]), "+f"(c[1]), "+f"(c[2]), "+f"(c[3])
        : "r"(a[0]), "r"(a[1]), "r"(a[2]), "r"(a[3]), "r"(b0), "r"(b1));
}
__device__ __forceinline__ uint32_t bf16x2(float lo, float hi) {
    uint32_t r;
    asm("cvt.rn.bf16x2.f32 %0, %1, %2;" : "=r"(r) : "f"(hi), "f"(lo));
    return r;
}

// ------------------------------ GEMM kernel ---------------------------------
// D[m][n] = sum_k A[m][k]*B[n][k] over 3 segments (Ahi*Bhi + Ahi*Blo + Alo*Bhi),
// fp32 accumulated in registers.
// MODE 0: Cf = alpha*acc (batched via sC)
// MODE 1: hi/lo bf16 row-major out with bias
// MODE 2: hi/lo bf16 TRANSPOSED out with bias (v proj -> vT[b][n][t])
template <int MODE>
__global__ __launch_bounds__(256, 2)
void gemm_mma(const __nv_bfloat16* __restrict__ Ahi, const __nv_bfloat16* __restrict__ Alo,
              const __nv_bfloat16* __restrict__ Bhi, const __nv_bfloat16* __restrict__ Blo,
              float* __restrict__ Cf, __nv_bfloat16* __restrict__ Chi,
              __nv_bfloat16* __restrict__ Clo, const float* __restrict__ bias,
              float alpha, int K, int lda, int ldb, int ldc,
              long long sA, long long sB, long long sC)
{
    extern __shared__ uint8_t dynsm[];
    const uint32_t smA = s2u(dynsm);
    const uint32_t smB = smA + STAGES * STAGEB;

    const int tid = threadIdx.x;
    const int wid = tid >> 5, lane = tid & 31;
    const int wm = wid & 1;            // 2 warp rows of 64
    const int wn = wid >> 1;           // 4 warp cols of 32
    const int m0 = blockIdx.y * 128, n0 = blockIdx.x * 128;
    const int z = blockIdx.z;
    Ahi += (long long)z * sA;  Alo += (long long)z * sA;
    Bhi += (long long)z * sB;  Blo += (long long)z * sB;

    const int kc = K >> 5;             // 32-wide chunks per segment
    const int nch = 3 * kc;
    const __nv_bfloat16* Aseg[3] = { Ahi, Ahi, Alo };
    const __nv_bfloat16* Bseg[3] = { Bhi, Blo, Bhi };

    float acc[4][4][4];
#pragma unroll
    for (int i = 0; i < 4; i++)
#pragma unroll
        for (int j = 0; j < 4; j++)
#pragma unroll
            for (int q = 0; q < 4; q++) acc[i][j][q] = 0.0f;

    // loader: 128 rows x 32 cols bf16 per operand = 512 x 16B; 2 per thread
    const int lrow = tid >> 2;         // wrong stride fix below: 256 threads/4 = 64..
    const int lcg = tid & 3;
    auto load = [&](int c) {
        const int st = c % STAGES;
        const int seg = c / kc;
        const int kk = (c - seg * kc) << 5;
        const __nv_bfloat16* Ap = Aseg[seg];
        const __nv_bfloat16* Bp = Bseg[seg];
        const uint32_t sa = smA + st * STAGEB;
        const uint32_t sb = smB + st * STAGEB;
#pragma unroll
        for (int i = 0; i < 2; i++) {
            const int row = lrow + i * 64;
            const uint32_t off = row * ROWB + lcg * 16;
            cp16(sa + off, Ap + (long long)(m0 + row) * lda + kk + lcg * 8);
            cp16(sb + off, Bp + (long long)(n0 + row) * ldb + kk + lcg * 8);
        }
        cp_commit();
    };

    load(0);
    load(1);

    const int lrow16 = lane & 15;              // ldmatrix row within 16
    const int lkhalf = (lane >> 4) * 16;       // byte offset of k-half (8 bf16)

    for (int c = 0; c < nch; c++) {
        cp_wait<PRE - 1>();
        __syncthreads();
        const int cp = c + PRE;
        if (cp < nch) load(cp);

        const int st = c % STAGES;
        const uint32_t stA = smA + st * STAGEB;
        const uint32_t stB = smB + st * STAGEB;
#pragma unroll
        for (int ks = 0; ks < 2; ks++) {
            const uint32_t colb = ks * 32 + lkhalf;
            uint32_t a[4][4], b[2][4];
#pragma unroll
            for (int mt = 0; mt < 4; mt++)
                ldsm4(a[mt], stA + (wm * 64 + mt * 16 + lrow16) * ROWB + colb);
#pragma unroll
            for (int nb = 0; nb < 2; nb++)
                ldsm4(b[nb], stB + (wn * 32 + nb * 16 + lrow16) * ROWB + colb);
#pragma unroll
            for (int mt = 0; mt < 4; mt++)
#pragma unroll
                for (int nt = 0; nt < 4; nt++)
                    mma16816(acc[mt][nt], a[mt], b[nt >> 1][nt & 1],
                             b[nt >> 1][2 + (nt & 1)]);
        }
    }

    // ------------------------------- epilogue -------------------------------
    const int qr = lane >> 2;          // row within 8
    const int qc = (lane & 3) * 2;     // col pair
#pragma unroll
    for (int mt = 0; mt < 4; mt++) {
        const int mA = m0 + wm * 64 + mt * 16 + qr;
#pragma unroll
        for (int nt = 0; nt < 4; nt++) {
            const int n = n0 + wn * 32 + nt * 8 + qc;
            const float* a4 = acc[mt][nt];
            if (MODE == 0) {
                float* base = Cf + (long long)z * sC;
                float2 s0 = { alpha * a4[0], alpha * a4[1] };
                float2 s1 = { alpha * a4[2], alpha * a4[3] };
                *(float2*)&base[(long long)mA * ldc + n] = s0;
                *(float2*)&base[(long long)(mA + 8) * ldc + n] = s1;
            } else if (MODE == 1) {
                const float b0 = __ldg(&bias[n]), b1 = __ldg(&bias[n + 1]);
#pragma unroll
                for (int h = 0; h < 2; h++) {
                    const long long r = (long long)(mA + h * 8) * ldc + n;
                    const float o0 = a4[h * 2 + 0] + b0;
                    const float o1 = a4[h * 2 + 1] + b1;
                    const __nv_bfloat16 h0 = __float2bfloat16(o0);
                    const __nv_bfloat16 h1 = __float2bfloat16(o1);
                    *(uint32_t*)&Chi[r] =
                        (uint32_t)*(const uint16_t*)&h0 |
                        ((uint32_t)*(const uint16_t*)&h1 << 16);
                    const __nv_bfloat16 l0 = __float2bfloat16(o0 - __bfloat162float(h0));
                    const __nv_bfloat16 l1 = __float2bfloat16(o1 - __bfloat162float(h1));
                    *(uint32_t*)&Clo[r] =
                        (uint32_t)*(const uint16_t*)&l0 |
                        ((uint32_t)*(const uint16_t*)&l1 << 16);
                }
            } else {
                const float b0 = __ldg(&bias[n]), b1 = __ldg(&bias[n + 1]);
#pragma unroll
                for (int h = 0; h < 2; h++) {
                    const int m = mA + h * 8;
                    const int bt = m >> 11, tt = m & (SEQ - 1);
                    const long long cb = (long long)bt * DIM * SEQ + tt;
                    const float o0 = a4[h * 2 + 0] + b0;
                    const float o1 = a4[h * 2 + 1] + b1;
                    const __nv_bfloat16 h0 = __float2bfloat16(o0);
                    const __nv_bfloat16 h1 = __float2bfloat16(o1);
                    Chi[cb + (long long)n * SEQ] = h0;
                    Chi[cb + (long long)(n + 1) * SEQ] = h1;
                    Clo[cb + (long long)n * SEQ] =
                        __float2bfloat16(o0 - __bfloat162float(h0));
                    Clo[cb + (long long)(n + 1) * SEQ] =
                        __float2bfloat16(o1 - __bfloat162float(h1));
                }
            }
        }
    }
}

// --------------------------- fp32 -> hi/lo split ----------------------------
__global__ __launch_bounds__(256) void split_f32(const float4* __restrict__ x,
                                                 uint2* __restrict__ hi,
                                                 uint2* __restrict__ lo, int n4)
{
    for (int i = blockIdx.x * blockDim.x + threadIdx.x; i < n4;
         i += gridDim.x * blockDim.x) {
        const float4 v = x[i];
        __align__(8) __nv_bfloat16 h[4], l[4];
        const float vv[4] = { v.x, v.y, v.z, v.w };
#pragma unroll
        for (int j = 0; j < 4; j++) {
            const __nv_bfloat16 hh = __float2bfloat16(vv[j]);
            h[j] = hh;
            l[j] = __float2bfloat16(vv[j] - __bfloat162float(hh));
        }
        hi[i] = *(const uint2*)h;
        lo[i] = *(const uint2*)l;
    }
}

// -------------- row softmax over T=2048, emits hi/lo bf16 probs -------------
__global__ __launch_bounds__(256) void softmax_rows(const float* __restrict__ S,
                                                    __nv_bfloat16* __restrict__ Phi,
                                                    __nv_bfloat16* __restrict__ Plo)
{
    const long long row = (long long)blockIdx.x * SEQ;
    const float* p = S + row;
    const int tid = threadIdx.x;
    const int lane = tid & 31, wid = tid >> 5;

    float v[8];
    *(float4*)&v[0] = *(const float4*)&p[tid * 8];
    *(float4*)&v[4] = *(const float4*)&p[tid * 8 + 4];

    __shared__ float red[8];
    float m = v[0];
#pragma unroll
    for (int i = 1; i < 8; i++) m = fmaxf(m, v[i]);
#pragma unroll
    for (int o = 16; o > 0; o >>= 1) m = fmaxf(m, __shfl_xor_sync(0xffffffffu, m, o));
    if (lane == 0) red[wid] = m;
    __syncthreads();
    m = red[0];
#pragma unroll
    for (int i = 1; i < 8; i++) m = fmaxf(m, red[i]);
    __syncthreads();

    float s = 0.0f;
#pragma unroll
    for (int i = 0; i < 8; i++) { v[i] = expf(v[i] - m); s += v[i]; }
#pragma unroll
    for (int o = 16; o > 0; o >>= 1) s += __shfl_xor_sync(0xffffffffu, s, o);
    if (lane == 0) red[wid] = s;
    __syncthreads();
    s = 0.0f;
#pragma unroll
    for (int i = 0; i < 8; i++) s += red[i];
    const float inv = 1.0f / s;

    __align__(16) __nv_bfloat16 h[8], l[8];
#pragma unroll
    for (int i = 0; i < 8; i++) {
        const float o = v[i] * inv;
        const __nv_bfloat16 hh = __float2bfloat16(o);
        h[i] = hh;
        l[i] = __float2bfloat16(o - __bfloat162float(hh));
    }
    *(uint4*)(Phi + row + tid * 8) = *(const uint4*)h;
    *(uint4*)(Plo + row + tid * 8) = *(const uint4*)l;
}

// --------------------------------- launch -----------------------------------
extern "C" void kernel_launch(void* const* d_in, const int* in_sizes, int n_in,
                              void* d_out, int out_size)
{
    const float* q_in = (const float*)d_in[0];
    const float* k_in = (const float*)d_in[1];
    const float* v_in = (const float*)d_in[2];
    const float* W    = (const float*)d_in[3];
    const float* bias = (const float*)d_in[4];
    float* out = (float*)d_out;

    __nv_bfloat16 *xq_hi, *xq_lo, *xk_hi, *xk_lo, *xv_hi, *xv_lo;
    __nv_bfloat16 *w_hi, *w_lo, *q_hi, *q_lo, *k_hi, *k_lo, *vT_hi, *vT_lo;
    __nv_bfloat16 *p_hi, *p_lo;
    float* sbuf;
    cudaGetSymbolAddress((void**)&xq_hi, g_xq_hi); cudaGetSymbolAddress((void**)&xq_lo, g_xq_lo);
    cudaGetSymbolAddress((void**)&xk_hi, g_xk_hi); cudaGetSymbolAddress((void**)&xk_lo, g_xk_lo);
    cudaGetSymbolAddress((void**)&xv_hi, g_xv_hi); cudaGetSymbolAddress((void**)&xv_lo, g_xv_lo);
    cudaGetSymbolAddress((void**)&w_hi,  g_W_hi);  cudaGetSymbolAddress((void**)&w_lo,  g_W_lo);
    cudaGetSymbolAddress((void**)&q_hi,  g_q_hi);  cudaGetSymbolAddress((void**)&q_lo,  g_q_lo);
    cudaGetSymbolAddress((void**)&k_hi,  g_k_hi);  cudaGetSymbolAddress((void**)&k_lo,  g_k_lo);
    cudaGetSymbolAddress((void**)&vT_hi, g_vT_hi); cudaGetSymbolAddress((void**)&vT_lo, g_vT_lo);
    cudaGetSymbolAddress((void**)&p_hi,  g_p_hi);  cudaGetSymbolAddress((void**)&p_lo,  g_p_lo);
    cudaGetSymbolAddress((void**)&sbuf,  g_s);

    cudaFuncSetAttribute(gemm_mma<0>, cudaFuncAttributeMaxDynamicSharedMemorySize, SMEM_DYN);
    cudaFuncSetAttribute(gemm_mma<1>, cudaFuncAttributeMaxDynamicSharedMemorySize, SMEM_DYN);
    cudaFuncSetAttribute(gemm_mma<2>, cudaFuncAttributeMaxDynamicSharedMemorySize, SMEM_DYN);

    const int n4 = (int)(ND / 4);
    split_f32<<<1024, 256>>>((const float4*)q_in, (uint2*)xq_hi, (uint2*)xq_lo, n4);
    split_f32<<<1024, 256>>>((const float4*)k_in, (uint2*)xk_hi, (uint2*)xk_lo, n4);
    split_f32<<<1024, 256>>>((const float4*)v_in, (uint2*)xv_hi, (uint2*)xv_lo, n4);
    split_f32<<<256, 256>>>((const float4*)W, (uint2*)w_hi, (uint2*)w_lo, DIM * DIM / 4);

    // Projections: [8192, 1024] = X @ W^T + b, emit hi/lo (v transposed)
    {
        dim3 g(DIM / 128, (NBATCH * SEQ) / 128, 1);
        gemm_mma<1><<<g, 256, SMEM_DYN>>>(xq_hi, xq_lo, w_hi, w_lo,
                                          nullptr, q_hi, q_lo, bias, 1.0f,
                                          DIM, DIM, DIM, DIM, 0, 0, 0);
        gemm_mma<1><<<g, 256, SMEM_DYN>>>(xk_hi, xk_lo, w_hi, w_lo,
                                          nullptr, k_hi, k_lo, bias, 1.0f,
                                          DIM, DIM, DIM, DIM, 0, 0, 0);
        gemm_mma<2><<<g, 256, SMEM_DYN>>>(xv_hi, xv_lo, w_hi, w_lo,
                                          nullptr, vT_hi, vT_lo, bias, 1.0f,
                                          DIM, DIM, DIM, 0, 0, 0, 0);
    }

    // Scores: S[n] = (q[n] @ k[n]^T) / 32
    {
        dim3 g(SEQ / 128, SEQ / 128, NBATCH);
        gemm_mma<0><<<g, 256, SMEM_DYN>>>(q_hi, q_lo, k_hi, k_lo,
                                          sbuf, nullptr, nullptr, nullptr,
                                          1.0f / 32.0f, DIM, DIM, DIM, SEQ,
                                          (long long)SEQ * DIM, (long long)SEQ * DIM,
                                          (long long)SEQ * SEQ);
    }

    // Softmax -> hi/lo probs
    softmax_rows<<<NBATCH * SEQ, 256>>>(sbuf, p_hi, p_lo);

    // PV: y[n] = P[n] @ v[n]  (B = vT, K = 2048)
    {
        dim3 g(DIM / 128, SEQ / 128, NBATCH);
        gemm_mma<0><<<g, 256, SMEM_DYN>>>(p_hi, p_lo, vT_hi, vT_lo,
                                          out, nullptr, nullptr, nullptr,
                                          1.0f, SEQ, SEQ, SEQ, DIM,
                                          (long long)SEQ * SEQ, (long long)DIM * SEQ,
                                          (long long)SEQ * DIM);
    }
}

// round 9
// speedup vs baseline: 2.3209x; 1.1226x over previous
#include <cuda_runtime.h>
#include <cuda_bf16.h>
#include <stdint.h>
#include <math.h>

// ============================================================================
// AttentionLayer via mma.sync (HMMA) bf16 split (hi/lo) GEMMs, fp32 accum.
//   y = softmax((XqW^T+b)(XkW^T+b)^T / 32) (XvW^T+b)
// N=4, S=T=2048, D=1024.  Harness PTX target is plain sm_103 -> no tcgen05.
// R6: ldmatrix.trans PV path (v stays row-major; scatter epilogue removed),
//     merged q/k/v projection launch (wave quantization).
// ============================================================================

#define NBATCH 4
#define SEQ    2048
#define DIM    1024

#define STAGES 3
#define PRE    2
#define ROWB   80                 // 32 bf16 = 64B + 16B pad -> conflict-free LDSM
#define ROWBT  272                // 128 bf16 = 256B + 16B pad (trans B tiles)
#define STAGEB (128 * ROWB)       // 10240 B per operand stage
#define SMEM_DYN (STAGES * 2 * STAGEB)   // 61440

// ------------------------- scratch (__device__ globals) ---------------------
#define ND ((long long)NBATCH * SEQ * DIM)   // 8,388,608
#define NS ((long long)NBATCH * SEQ * SEQ)   // 16,777,216

// packed q|k|v slabs so one projection launch covers all three via blockIdx.z
__device__ __align__(256) __nv_bfloat16 g_xin_hi[3 * ND], g_xin_lo[3 * ND];
__device__ __align__(256) __nv_bfloat16 g_qkv_hi[3 * ND], g_qkv_lo[3 * ND];
__device__ __align__(256) __nv_bfloat16 g_W_hi[DIM * DIM], g_W_lo[DIM * DIM];
__device__ __align__(256) float         g_s[NS];
__device__ __align__(256) __nv_bfloat16 g_p_hi[NS], g_p_lo[NS];

// ------------------------------ PTX helpers ---------------------------------
__device__ __forceinline__ uint32_t s2u(const void* p) {
    uint32_t a;
    asm("{ .reg .u64 t; cvta.to.shared.u64 t, %1; cvt.u32.u64 %0, t; }"
        : "=r"(a) : "l"(p));
    return a;
}
__device__ __forceinline__ void cp16(uint32_t s, const void* g) {
    asm volatile("cp.async.cg.shared.global [%0], [%1], 16;" :: "r"(s), "l"(g) : "memory");
}
__device__ __forceinline__ void cp_commit() {
    asm volatile("cp.async.commit_group;" ::: "memory");
}
template <int N> __device__ __forceinline__ void cp_wait() {
    asm volatile("cp.async.wait_group %0;" :: "n"(N) : "memory");
}
__device__ __forceinline__ void ldsm4(uint32_t* r, uint32_t a) {
    asm volatile("ldmatrix.sync.aligned.m8n8.x4.shared.b16 {%0,%1,%2,%3}, [%4];"
                 : "=r"(r[0]), "=r"(r[1]), "=r"(r[2]), "=r"(r[3]) : "r"(a));
}
__device__ __forceinline__ void ldsm4t(uint32_t* r, uint32_t a) {
    asm volatile("ldmatrix.sync.aligned.m8n8.x4.trans.shared.b16 {%0,%1,%2,%3}, [%4];"
                 : "=r"(r[0]), "=r"(r[1]), "=r"(r[2]), "=r"(r[3]) : "r"(a));
}
__device__ __forceinline__ void mma16816(float* c, const uint32_t* a,
                                         uint32_t b0, uint32_t b1) {
    asm volatile(
        "mma.sync.aligned.m16n8k16.row.col.f32.bf16.bf16.f32 "
        "{%0,%1,%2,%3},{%4,%5,%6,%7},{%8,%9},{%0,%1,%2,%3};"
        : "+f"(c[0]), "+f"(c[1]), "+f"(c[2]), "+f"(c[3])
        : "r"(a[0]), "r"(a[1]), "r"(a[2]), "r"(a[3]), "r"(b0), "r"(b1));
}

// ------------------------------ GEMM kernel ---------------------------------
// D[m][n] = sum_k A[m][k]*B[n][k] over 3 segments (Ahi*Bhi + Ahi*Blo + Alo*Bhi),
// fp32 accumulated in registers.
// BT=0: B stored [n][k] row-major (NT), loaded with plain ldmatrix.
// BT=1: B stored [k][n] row-major (NN), loaded with ldmatrix.trans.
// MODE 0: Cf = alpha*acc (batched via sC)
// MODE 1: hi/lo bf16 row-major out with bias (batched via sC; bias shared)
template <int MODE, int BT>
__global__ __launch_bounds__(256, 2)
void gemm_mma(const __nv_bfloat16* __restrict__ Ahi, const __nv_bfloat16* __restrict__ Alo,
              const __nv_bfloat16* __restrict__ Bhi, const __nv_bfloat16* __restrict__ Blo,
              float* __restrict__ Cf, __nv_bfloat16* __restrict__ Chi,
              __nv_bfloat16* __restrict__ Clo, const float* __restrict__ bias,
              float alpha, int K, int lda, int ldb, int ldc,
              long long sA, long long sB, long long sC)
{
    extern __shared__ uint8_t dynsm[];
    const uint32_t smA = s2u(dynsm);
    const uint32_t smB = smA + STAGES * STAGEB;

    const int tid = threadIdx.x;
    const int wid = tid >> 5, lane = tid & 31;
    const int wm = wid & 1;            // 2 warp rows of 64
    const int wn = wid >> 1;           // 4 warp cols of 32
    const int m0 = blockIdx.y * 128, n0 = blockIdx.x * 128;
    const int z = blockIdx.z;
    Ahi += (long long)z * sA;  Alo += (long long)z * sA;
    Bhi += (long long)z * sB;  Blo += (long long)z * sB;

    const int kc = K >> 5;             // 32-wide chunks per segment
    const int nch = 3 * kc;
    const __nv_bfloat16* Aseg[3] = { Ahi, Ahi, Alo };
    const __nv_bfloat16* Bseg[3] = { Bhi, Blo, Bhi };

    float acc[4][4][4];
#pragma unroll
    for (int i = 0; i < 4; i++)
#pragma unroll
        for (int j = 0; j < 4; j++)
#pragma unroll
            for (int q = 0; q < 4; q++) acc[i][j][q] = 0.0f;

    const int lrow = tid >> 2;         // A loader: 64 rows per iter
    const int lcg = tid & 3;
    const int trow = tid >> 4;         // BT loader: 16 rows per iter, 256B rows
    const int tcg = tid & 15;
    auto load = [&](int c) {
        const int st = c % STAGES;
        const int seg = c / kc;
        const int kk = (c - seg * kc) << 5;
        const __nv_bfloat16* Ap = Aseg[seg];
        const __nv_bfloat16* Bp = Bseg[seg];
        const uint32_t sa = smA + st * STAGEB;
        const uint32_t sb = smB + st * STAGEB;
#pragma unroll
        for (int i = 0; i < 2; i++) {
            const int row = lrow + i * 64;
            cp16(sa + row * ROWB + lcg * 16,
                 Ap + (long long)(m0 + row) * lda + kk + lcg * 8);
        }
        if (BT) {
            // B tile = v[kk..kk+32][n0..n0+128], row-major, 256B rows
#pragma unroll
            for (int i = 0; i < 2; i++) {
                const int row = trow + i * 16;
                cp16(sb + row * ROWBT + tcg * 16,
                     Bp + (long long)(kk + row) * ldb + n0 + tcg * 8);
            }
        } else {
#pragma unroll
            for (int i = 0; i < 2; i++) {
                const int row = lrow + i * 64;
                cp16(sb + row * ROWB + lcg * 16,
                     Bp + (long long)(n0 + row) * ldb + kk + lcg * 8);
            }
        }
        cp_commit();
    };

    load(0);
    load(1);

    const int lrow16 = lane & 15;              // ldmatrix row within 16
    const int lhalf = lane >> 4;

    for (int c = 0; c < nch; c++) {
        cp_wait<PRE - 1>();
        __syncthreads();
        const int cp = c + PRE;
        if (cp < nch) load(cp);

        const int st = c % STAGES;
        const uint32_t stA = smA + st * STAGEB;
        const uint32_t stB = smB + st * STAGEB;
#pragma unroll
        for (int ks = 0; ks < 2; ks++) {
            uint32_t a[4][4], b[2][4];
#pragma unroll
            for (int mt = 0; mt < 4; mt++)
                ldsm4(a[mt], stA + (wm * 64 + mt * 16 + lrow16) * ROWB
                                 + ks * 32 + lhalf * 16);
            if (BT) {
                // trans: rows are k, cols are n; regs (0,1)=n-sub0 k-halves,
                // (2,3)=n-sub1 k-halves
#pragma unroll
                for (int pair = 0; pair < 2; pair++)
                    ldsm4t(b[pair], stB + (ks * 16 + lrow16) * ROWBT
                                        + (wn * 32 + pair * 16 + lhalf * 8) * 2);
#pragma unroll
                for (int mt = 0; mt < 4; mt++)
#pragma unroll
                    for (int nt = 0; nt < 4; nt++)
                        mma16816(acc[mt][nt], a[mt],
                                 b[nt >> 1][(nt & 1) * 2],
                                 b[nt >> 1][(nt & 1) * 2 + 1]);
            } else {
#pragma unroll
                for (int nb = 0; nb < 2; nb++)
                    ldsm4(b[nb], stB + (wn * 32 + nb * 16 + lrow16) * ROWB
                                     + ks * 32 + lhalf * 16);
#pragma unroll
                for (int mt = 0; mt < 4; mt++)
#pragma unroll
                    for (int nt = 0; nt < 4; nt++)
                        mma16816(acc[mt][nt], a[mt],
                                 b[nt >> 1][nt & 1],
                                 b[nt >> 1][2 + (nt & 1)]);
            }
        }
    }

    // ------------------------------- epilogue -------------------------------
    const int qr = lane >> 2;          // row within 8
    const int qc = (lane & 3) * 2;     // col pair
#pragma unroll
    for (int mt = 0; mt < 4; mt++) {
        const int mA = m0 + wm * 64 + mt * 16 + qr;
#pragma unroll
        for (int nt = 0; nt < 4; nt++) {
            const int n = n0 + wn * 32 + nt * 8 + qc;
            const float* a4 = acc[mt][nt];
            if (MODE == 0) {
                float* base = Cf + (long long)z * sC;
                float2 s0 = { alpha * a4[0], alpha * a4[1] };
                float2 s1 = { alpha * a4[2], alpha * a4[3] };
                *(float2*)&base[(long long)mA * ldc + n] = s0;
                *(float2*)&base[(long long)(mA + 8) * ldc + n] = s1;
            } else {
                const float b0 = __ldg(&bias[n]), b1 = __ldg(&bias[n + 1]);
                __nv_bfloat16* oh = Chi + (long long)z * sC;
                __nv_bfloat16* ol = Clo + (long long)z * sC;
#pragma unroll
                for (int h = 0; h < 2; h++) {
                    const long long r = (long long)(mA + h * 8) * ldc + n;
                    const float o0 = a4[h * 2 + 0] + b0;
                    const float o1 = a4[h * 2 + 1] + b1;
                    const __nv_bfloat16 h0 = __float2bfloat16(o0);
                    const __nv_bfloat16 h1 = __float2bfloat16(o1);
                    *(uint32_t*)&oh[r] =
                        (uint32_t)*(const uint16_t*)&h0 |
                        ((uint32_t)*(const uint16_t*)&h1 << 16);
                    const __nv_bfloat16 l0 = __float2bfloat16(o0 - __bfloat162float(h0));
                    const __nv_bfloat16 l1 = __float2bfloat16(o1 - __bfloat162float(h1));
                    *(uint32_t*)&ol[r] =
                        (uint32_t)*(const uint16_t*)&l0 |
                        ((uint32_t)*(const uint16_t*)&l1 << 16);
                }
            }
        }
    }
}

// --------------------------- fp32 -> hi/lo split ----------------------------
__global__ __launch_bounds__(256) void split_f32(const float4* __restrict__ x,
                                                 uint2* __restrict__ hi,
                                                 uint2* __restrict__ lo, int n4)
{
    for (int i = blockIdx.x * blockDim.x + threadIdx.x; i < n4;
         i += gridDim.x * blockDim.x) {
        const float4 v = x[i];
        __align__(8) __nv_bfloat16 h[4], l[4];
        const float vv[4] = { v.x, v.y, v.z, v.w };
#pragma unroll
        for (int j = 0; j < 4; j++) {
            const __nv_bfloat16 hh = __float2bfloat16(vv[j]);
            h[j] = hh;
            l[j] = __float2bfloat16(vv[j] - __bfloat162float(hh));
        }
        hi[i] = *(const uint2*)h;
        lo[i] = *(const uint2*)l;
    }
}

// -------------- row softmax over T=2048, emits hi/lo bf16 probs -------------
__global__ __launch_bounds__(256) void softmax_rows(const float* __restrict__ S,
                                                    __nv_bfloat16* __restrict__ Phi,
                                                    __nv_bfloat16* __restrict__ Plo)
{
    const long long row = (long long)blockIdx.x * SEQ;
    const float* p = S + row;
    const int tid = threadIdx.x;
    const int lane = tid & 31, wid = tid >> 5;

    float v[8];
    *(float4*)&v[0] = *(const float4*)&p[tid * 8];
    *(float4*)&v[4] = *(const float4*)&p[tid * 8 + 4];

    __shared__ float red[8];
    float m = v[0];
#pragma unroll
    for (int i = 1; i < 8; i++) m = fmaxf(m, v[i]);
#pragma unroll
    for (int o = 16; o > 0; o >>= 1) m = fmaxf(m, __shfl_xor_sync(0xffffffffu, m, o));
    if (lane == 0) red[wid] = m;
    __syncthreads();
    m = red[0];
#pragma unroll
    for (int i = 1; i < 8; i++) m = fmaxf(m, red[i]);
    __syncthreads();

    float s = 0.0f;
#pragma unroll
    for (int i = 0; i < 8; i++) { v[i] = expf(v[i] - m); s += v[i]; }
#pragma unroll
    for (int o = 16; o > 0; o >>= 1) s += __shfl_xor_sync(0xffffffffu, s, o);
    if (lane == 0) red[wid] = s;
    __syncthreads();
    s = 0.0f;
#pragma unroll
    for (int i = 0; i < 8; i++) s += red[i];
    const float inv = 1.0f / s;

    __align__(16) __nv_bfloat16 h[8], l[8];
#pragma unroll
    for (int i = 0; i < 8; i++) {
        const float o = v[i] * inv;
        const __nv_bfloat16 hh = __float2bfloat16(o);
        h[i] = hh;
        l[i] = __float2bfloat16(o - __bfloat162float(hh));
    }
    *(uint4*)(Phi + row + tid * 8) = *(const uint4*)h;
    *(uint4*)(Plo + row + tid * 8) = *(const uint4*)l;
}

// --------------------------------- launch -----------------------------------
extern "C" void kernel_launch(void* const* d_in, const int* in_sizes, int n_in,
                              void* d_out, int out_size)
{
    const float* q_in = (const float*)d_in[0];
    const float* k_in = (const float*)d_in[1];
    const float* v_in = (const float*)d_in[2];
    const float* W    = (const float*)d_in[3];
    const float* bias = (const float*)d_in[4];
    float* out = (float*)d_out;

    __nv_bfloat16 *xin_hi, *xin_lo, *qkv_hi, *qkv_lo, *w_hi, *w_lo, *p_hi, *p_lo;
    float* sbuf;
    cudaGetSymbolAddress((void**)&xin_hi, g_xin_hi);
    cudaGetSymbolAddress((void**)&xin_lo, g_xin_lo);
    cudaGetSymbolAddress((void**)&qkv_hi, g_qkv_hi);
    cudaGetSymbolAddress((void**)&qkv_lo, g_qkv_lo);
    cudaGetSymbolAddress((void**)&w_hi,  g_W_hi);
    cudaGetSymbolAddress((void**)&w_lo,  g_W_lo);
    cudaGetSymbolAddress((void**)&p_hi,  g_p_hi);
    cudaGetSymbolAddress((void**)&p_lo,  g_p_lo);
    cudaGetSymbolAddress((void**)&sbuf,  g_s);

    cudaFuncSetAttribute(gemm_mma<0, 0>, cudaFuncAttributeMaxDynamicSharedMemorySize, SMEM_DYN);
    cudaFuncSetAttribute(gemm_mma<1, 0>, cudaFuncAttributeMaxDynamicSharedMemorySize, SMEM_DYN);
    cudaFuncSetAttribute(gemm_mma<0, 1>, cudaFuncAttributeMaxDynamicSharedMemorySize, SMEM_DYN);

    const int n4 = (int)(ND / 4);
    split_f32<<<1024, 256>>>((const float4*)q_in, (uint2*)xin_hi, (uint2*)xin_lo, n4);
    split_f32<<<1024, 256>>>((const float4*)k_in, (uint2*)(xin_hi + ND), (uint2*)(xin_lo + ND), n4);
    split_f32<<<1024, 256>>>((const float4*)v_in, (uint2*)(xin_hi + 2 * ND), (uint2*)(xin_lo + 2 * ND), n4);
    split_f32<<<256, 256>>>((const float4*)W, (uint2*)w_hi, (uint2*)w_lo, DIM * DIM / 4);

    // Projections (q,k,v in one launch via z): [8192,1024] = X @ W^T + b
    {
        dim3 g(DIM / 128, (NBATCH * SEQ) / 128, 3);
        gemm_mma<1, 0><<<g, 256, SMEM_DYN>>>(xin_hi, xin_lo, w_hi, w_lo,
                                             nullptr, qkv_hi, qkv_lo, bias, 1.0f,
                                             DIM, DIM, DIM, DIM, ND, 0, ND);
    }

    const __nv_bfloat16* q_hi = qkv_hi;          const __nv_bfloat16* q_lo = qkv_lo;
    const __nv_bfloat16* k_hi = qkv_hi + ND;     const __nv_bfloat16* k_lo = qkv_lo + ND;
    const __nv_bfloat16* v_hi = qkv_hi + 2 * ND; const __nv_bfloat16* v_lo = qkv_lo + 2 * ND;

    // Scores: S[n] = (q[n] @ k[n]^T) / 32
    {
        dim3 g(SEQ / 128, SEQ / 128, NBATCH);
        gemm_mma<0, 0><<<g, 256, SMEM_DYN>>>(q_hi, q_lo, k_hi, k_lo,
                                             sbuf, nullptr, nullptr, nullptr,
                                             1.0f / 32.0f, DIM, DIM, DIM, SEQ,
                                             (long long)SEQ * DIM, (long long)SEQ * DIM,
                                             (long long)SEQ * SEQ);
    }

    // Softmax -> hi/lo probs
    softmax_rows<<<NBATCH * SEQ, 256>>>(sbuf, p_hi, p_lo);

    // PV: y[n] = P[n] @ v[n]; v row-major [t][d] consumed via ldmatrix.trans
    {
        dim3 g(DIM / 128, SEQ / 128, NBATCH);
        gemm_mma<0, 1><<<g, 256, SMEM_DYN>>>(p_hi, p_lo, v_hi, v_lo,
                                             out, nullptr, nullptr, nullptr,
                                             1.0f, SEQ, SEQ, DIM, DIM,
                                             (long long)SEQ * SEQ, (long long)SEQ * DIM,
                                             (long long)SEQ * DIM);
    }
}

// round 12
// speedup vs baseline: 2.5108x; 1.0818x over previous
#include <cuda_runtime.h>
#include <cuda_bf16.h>
#include <stdint.h>
#include <math.h>

// ============================================================================
// AttentionLayer via mma.sync (HMMA) bf16 split (hi/lo) GEMMs, fp32 accum.
//   y = softmax((XqW^T+b)(XkW^T+b)^T / 32) (XvW^T+b)
// N=4, S=T=2048, D=1024.  Harness PTX target is plain sm_103 -> no tcgen05.
// R10: BK=64 (half the barriers, longer MMA runs), STAGES=2, merged split.
// ============================================================================

#define NBATCH 4
#define SEQ    2048
#define DIM    1024

#define STAGES 2
#define ROWB   144                // 64 bf16 = 128B + 16B pad -> conflict-free LDSM
#define ROWBT  272                // 128 bf16 = 256B + 16B pad (trans B tiles)
#define STAGEB (128 * ROWB)       // 18432 B per operand stage
#define SMEM_DYN (STAGES * 2 * STAGEB)   // 73728

// ------------------------- scratch (__device__ globals) ---------------------
#define ND ((long long)NBATCH * SEQ * DIM)   // 8,388,608
#define NS ((long long)NBATCH * SEQ * SEQ)   // 16,777,216

__device__ __align__(256) __nv_bfloat16 g_xin_hi[3 * ND], g_xin_lo[3 * ND];
__device__ __align__(256) __nv_bfloat16 g_qkv_hi[3 * ND], g_qkv_lo[3 * ND];
__device__ __align__(256) __nv_bfloat16 g_W_hi[DIM * DIM], g_W_lo[DIM * DIM];
__device__ __align__(256) float         g_s[NS];
__device__ __align__(256) __nv_bfloat16 g_p_hi[NS], g_p_lo[NS];

// ------------------------------ PTX helpers ---------------------------------
__device__ __forceinline__ uint32_t s2u(const void* p) {
    uint32_t a;
    asm("{ .reg .u64 t; cvta.to.shared.u64 t, %1; cvt.u32.u64 %0, t; }"
        : "=r"(a) : "l"(p));
    return a;
}
__device__ __forceinline__ void cp16(uint32_t s, const void* g) {
    asm volatile("cp.async.cg.shared.global [%0], [%1], 16;" :: "r"(s), "l"(g) : "memory");
}
__device__ __forceinline__ void cp_commit() {
    asm volatile("cp.async.commit_group;" ::: "memory");
}
template <int N> __device__ __forceinline__ void cp_wait() {
    asm volatile("cp.async.wait_group %0;" :: "n"(N) : "memory");
}
__device__ __forceinline__ void ldsm4(uint32_t* r, uint32_t a) {
    asm volatile("ldmatrix.sync.aligned.m8n8.x4.shared.b16 {%0,%1,%2,%3}, [%4];"
                 : "=r"(r[0]), "=r"(r[1]), "=r"(r[2]), "=r"(r[3]) : "r"(a));
}
__device__ __forceinline__ void ldsm4t(uint32_t* r, uint32_t a) {
    asm volatile("ldmatrix.sync.aligned.m8n8.x4.trans.shared.b16 {%0,%1,%2,%3}, [%4];"
                 : "=r"(r[0]), "=r"(r[1]), "=r"(r[2]), "=r"(r[3]) : "r"(a));
}
__device__ __forceinline__ void mma16816(float* c, const uint32_t* a,
                                         uint32_t b0, uint32_t b1) {
    asm volatile(
        "mma.sync.aligned.m16n8k16.row.col.f32.bf16.bf16.f32 "
        "{%0,%1,%2,%3},{%4,%5,%6,%7},{%8,%9},{%0,%1,%2,%3};"
        : "+f"(c[0]), "+f"(c[1]), "+f"(c[2]), "+f"(c[3])
        : "r"(a[0]), "r"(a[1]), "r"(a[2]), "r"(a[3]), "r"(b0), "r"(b1));
}

// ------------------------------ GEMM kernel ---------------------------------
// D[m][n] = sum_k A[m][k]*B[n][k] over 3 segments (Ahi*Bhi + Ahi*Blo + Alo*Bhi),
// fp32 accumulated in registers.  K processed in 64-wide chunks (4 MMA k-steps).
// BT=0: B stored [n][k] row-major (NT), plain ldmatrix.
// BT=1: B stored [k][n] row-major (NN), ldmatrix.trans.
// MODE 0: Cf = alpha*acc (batched via sC)
// MODE 1: hi/lo bf16 row-major out with bias (batched via sC; bias shared)
template <int MODE, int BT>
__global__ __launch_bounds__(256, 2)
void gemm_mma(const __nv_bfloat16* __restrict__ Ahi, const __nv_bfloat16* __restrict__ Alo,
              const __nv_bfloat16* __restrict__ Bhi, const __nv_bfloat16* __restrict__ Blo,
              float* __restrict__ Cf, __nv_bfloat16* __restrict__ Chi,
              __nv_bfloat16* __restrict__ Clo, const float* __restrict__ bias,
              float alpha, int K, int lda, int ldb, int ldc,
              long long sA, long long sB, long long sC)
{
    extern __shared__ uint8_t dynsm[];
    const uint32_t smA = s2u(dynsm);
    const uint32_t smB = smA + STAGES * STAGEB;

    const int tid = threadIdx.x;
    const int wid = tid >> 5, lane = tid & 31;
    const int wm = wid & 1;            // 2 warp rows of 64
    const int wn = wid >> 1;           // 4 warp cols of 32
    const int m0 = blockIdx.y * 128, n0 = blockIdx.x * 128;
    const int z = blockIdx.z;
    Ahi += (long long)z * sA;  Alo += (long long)z * sA;
    Bhi += (long long)z * sB;  Blo += (long long)z * sB;

    const int kc = K >> 6;             // 64-wide chunks per segment
    const int nch = 3 * kc;
    const __nv_bfloat16* Aseg[3] = { Ahi, Ahi, Alo };
    const __nv_bfloat16* Bseg[3] = { Bhi, Blo, Bhi };

    float acc[4][4][4];
#pragma unroll
    for (int i = 0; i < 4; i++)
#pragma unroll
        for (int j = 0; j < 4; j++)
#pragma unroll
            for (int q = 0; q < 4; q++) acc[i][j][q] = 0.0f;

    auto load = [&](int c) {
        const int st = c & 1;
        const int seg = c / kc;
        const int kk = (c - seg * kc) << 6;
        const __nv_bfloat16* Ap = Aseg[seg];
        const __nv_bfloat16* Bp = Bseg[seg];
        const uint32_t sa = smA + st * STAGEB;
        const uint32_t sb = smB + st * STAGEB;
        // A tile: 128 rows x 128B  (1024 x 16B transfers, 4/thread)
#pragma unroll
        for (int i = 0; i < 4; i++) {
            const int idx = tid + i * 256;
            const int row = idx >> 3, cg = idx & 7;
            cp16(sa + row * ROWB + cg * 16,
                 Ap + (long long)(m0 + row) * lda + kk + cg * 8);
        }
        if (BT) {
            // B tile: 64 rows x 256B (v[kk..kk+64][n0..n0+128])
#pragma unroll
            for (int i = 0; i < 4; i++) {
                const int idx = tid + i * 256;
                const int row = idx >> 4, cg = idx & 15;
                cp16(sb + row * ROWBT + cg * 16,
                     Bp + (long long)(kk + row) * ldb + n0 + cg * 8);
            }
        } else {
#pragma unroll
            for (int i = 0; i < 4; i++) {
                const int idx = tid + i * 256;
                const int row = idx >> 3, cg = idx & 7;
                cp16(sb + row * ROWB + cg * 16,
                     Bp + (long long)(n0 + row) * ldb + kk + cg * 8);
            }
        }
        cp_commit();
    };

    load(0);

    const int lrow16 = lane & 15;              // ldmatrix row within 16
    const int lhalf = lane >> 4;

    for (int c = 0; c < nch; c++) {
        cp_wait<0>();
        __syncthreads();
        if (c + 1 < nch) load(c + 1);

        const uint32_t stA = smA + (c & 1) * STAGEB;
        const uint32_t stB = smB + (c & 1) * STAGEB;
#pragma unroll
        for (int ks = 0; ks < 4; ks++) {
            uint32_t a[4][4], b[2][4];
#pragma unroll
            for (int mt = 0; mt < 4; mt++)
                ldsm4(a[mt], stA + (wm * 64 + mt * 16 + lrow16) * ROWB
                                 + ks * 32 + lhalf * 16);
            if (BT) {
#pragma unroll
                for (int pair = 0; pair < 2; pair++)
                    ldsm4t(b[pair], stB + (ks * 16 + lrow16) * ROWBT
                                        + (wn * 32 + pair * 16 + lhalf * 8) * 2);
#pragma unroll
                for (int mt = 0; mt < 4; mt++)
#pragma unroll
                    for (int nt = 0; nt < 4; nt++)
                        mma16816(acc[mt][nt], a[mt],
                                 b[nt >> 1][(nt & 1) * 2],
                                 b[nt >> 1][(nt & 1) * 2 + 1]);
            } else {
#pragma unroll
                for (int nb = 0; nb < 2; nb++)
                    ldsm4(b[nb], stB + (wn * 32 + nb * 16 + lrow16) * ROWB
                                     + ks * 32 + lhalf * 16);
#pragma unroll
                for (int mt = 0; mt < 4; mt++)
#pragma unroll
                    for (int nt = 0; nt < 4; nt++)
                        mma16816(acc[mt][nt], a[mt],
                                 b[nt >> 1][nt & 1],
                                 b[nt >> 1][2 + (nt & 1)]);
            }
        }
    }

    // ------------------------------- epilogue -------------------------------
    const int qr = lane >> 2;          // row within 8
    const int qc = (lane & 3) * 2;     // col pair
#pragma unroll
    for (int mt = 0; mt < 4; mt++) {
        const int mA = m0 + wm * 64 + mt * 16 + qr;
#pragma unroll
        for (int nt = 0; nt < 4; nt++) {
            const int n = n0 + wn * 32 + nt * 8 + qc;
            const float* a4 = acc[mt][nt];
            if (MODE == 0) {
                float* base = Cf + (long long)z * sC;
                float2 s0 = { alpha * a4[0], alpha * a4[1] };
                float2 s1 = { alpha * a4[2], alpha * a4[3] };
                *(float2*)&base[(long long)mA * ldc + n] = s0;
                *(float2*)&base[(long long)(mA + 8) * ldc + n] = s1;
            } else {
                const float b0 = __ldg(&bias[n]), b1 = __ldg(&bias[n + 1]);
                __nv_bfloat16* oh = Chi + (long long)z * sC;
                __nv_bfloat16* ol = Clo + (long long)z * sC;
#pragma unroll
                for (int h = 0; h < 2; h++) {
                    const long long r = (long long)(mA + h * 8) * ldc + n;
                    const float o0 = a4[h * 2 + 0] + b0;
                    const float o1 = a4[h * 2 + 1] + b1;
                    const __nv_bfloat16 h0 = __float2bfloat16(o0);
                    const __nv_bfloat16 h1 = __float2bfloat16(o1);
                    *(uint32_t*)&oh[r] =
                        (uint32_t)*(const uint16_t*)&h0 |
                        ((uint32_t)*(const uint16_t*)&h1 << 16);
                    const __nv_bfloat16 l0 = __float2bfloat16(o0 - __bfloat162float(h0));
                    const __nv_bfloat16 l1 = __float2bfloat16(o1 - __bfloat162float(h1));
                    *(uint32_t*)&ol[r] =
                        (uint32_t)*(const uint16_t*)&l0 |
                        ((uint32_t)*(const uint16_t*)&l1 << 16);
                }
            }
        }
    }
}

// ------------------ fp32 -> hi/lo split (q,k,v,W in one launch) -------------
__global__ __launch_bounds__(256) void split_all(
    const float4* __restrict__ q, const float4* __restrict__ k,
    const float4* __restrict__ v, const float4* __restrict__ w,
    uint2* __restrict__ xhi, uint2* __restrict__ xlo,
    uint2* __restrict__ whi, uint2* __restrict__ wlo, int n4, int n4w)
{
    const int z = blockIdx.z;
    const float4* src;
    uint2 *hi, *lo;
    int n;
    if (z < 3) {
        src = (z == 0) ? q : (z == 1) ? k : v;
        hi = xhi + (long long)z * (ND / 4);
        lo = xlo + (long long)z * (ND / 4);
        n = n4;
    } else {
        src = w; hi = whi; lo = wlo; n = n4w;
    }
    for (int i = blockIdx.x * blockDim.x + threadIdx.x; i < n;
         i += gridDim.x * blockDim.x) {
        const float4 val = src[i];
        __align__(8) __nv_bfloat16 h[4], l[4];
        const float vv[4] = { val.x, val.y, val.z, val.w };
#pragma unroll
        for (int j = 0; j < 4; j++) {
            const __nv_bfloat16 hh = __float2bfloat16(vv[j]);
            h[j] = hh;
            l[j] = __float2bfloat16(vv[j] - __bfloat162float(hh));
        }
        hi[i] = *(const uint2*)h;
        lo[i] = *(const uint2*)l;
    }
}

// -------------- row softmax over T=2048, emits hi/lo bf16 probs -------------
__global__ __launch_bounds__(256) void softmax_rows(const float* __restrict__ S,
                                                    __nv_bfloat16* __restrict__ Phi,
                                                    __nv_bfloat16* __restrict__ Plo)
{
    const long long row = (long long)blockIdx.x * SEQ;
    const float* p = S + row;
    const int tid = threadIdx.x;
    const int lane = tid & 31, wid = tid >> 5;

    float v[8];
    *(float4*)&v[0] = *(const float4*)&p[tid * 8];
    *(float4*)&v[4] = *(const float4*)&p[tid * 8 + 4];

    __shared__ float red[8];
    float m = v[0];
#pragma unroll
    for (int i = 1; i < 8; i++) m = fmaxf(m, v[i]);
#pragma unroll
    for (int o = 16; o > 0; o >>= 1) m = fmaxf(m, __shfl_xor_sync(0xffffffffu, m, o));
    if (lane == 0) red[wid] = m;
    __syncthreads();
    m = red[0];
#pragma unroll
    for (int i = 1; i < 8; i++) m = fmaxf(m, red[i]);
    __syncthreads();

    float s = 0.0f;
#pragma unroll
    for (int i = 0; i < 8; i++) { v[i] = expf(v[i] - m); s += v[i]; }
#pragma unroll
    for (int o = 16; o > 0; o >>= 1) s += __shfl_xor_sync(0xffffffffu, s, o);
    if (lane == 0) red[wid] = s;
    __syncthreads();
    s = 0.0f;
#pragma unroll
    for (int i = 0; i < 8; i++) s += red[i];
    const float inv = 1.0f / s;

    __align__(16) __nv_bfloat16 h[8], l[8];
#pragma unroll
    for (int i = 0; i < 8; i++) {
        const float o = v[i] * inv;
        const __nv_bfloat16 hh = __float2bfloat16(o);
        h[i] = hh;
        l[i] = __float2bfloat16(o - __bfloat162float(hh));
    }
    *(uint4*)(Phi + row + tid * 8) = *(const uint4*)h;
    *(uint4*)(Plo + row + tid * 8) = *(const uint4*)l;
}

// --------------------------------- launch -----------------------------------
extern "C" void kernel_launch(void* const* d_in, const int* in_sizes, int n_in,
                              void* d_out, int out_size)
{
    const float* q_in = (const float*)d_in[0];
    const float* k_in = (const float*)d_in[1];
    const float* v_in = (const float*)d_in[2];
    const float* W    = (const float*)d_in[3];
    const float* bias = (const float*)d_in[4];
    float* out = (float*)d_out;

    __nv_bfloat16 *xin_hi, *xin_lo, *qkv_hi, *qkv_lo, *w_hi, *w_lo, *p_hi, *p_lo;
    float* sbuf;
    cudaGetSymbolAddress((void**)&xin_hi, g_xin_hi);
    cudaGetSymbolAddress((void**)&xin_lo, g_xin_lo);
    cudaGetSymbolAddress((void**)&qkv_hi, g_qkv_hi);
    cudaGetSymbolAddress((void**)&qkv_lo, g_qkv_lo);
    cudaGetSymbolAddress((void**)&w_hi,  g_W_hi);
    cudaGetSymbolAddress((void**)&w_lo,  g_W_lo);
    cudaGetSymbolAddress((void**)&p_hi,  g_p_hi);
    cudaGetSymbolAddress((void**)&p_lo,  g_p_lo);
    cudaGetSymbolAddress((void**)&sbuf,  g_s);

    cudaFuncSetAttribute(gemm_mma<0, 0>, cudaFuncAttributeMaxDynamicSharedMemorySize, SMEM_DYN);
    cudaFuncSetAttribute(gemm_mma<1, 0>, cudaFuncAttributeMaxDynamicSharedMemorySize, SMEM_DYN);
    cudaFuncSetAttribute(gemm_mma<0, 1>, cudaFuncAttributeMaxDynamicSharedMemorySize, SMEM_DYN);

    // one split launch for q,k,v (z<3) and W (z=3)
    {
        dim3 g(256, 1, 4);
        split_all<<<g, 256>>>((const float4*)q_in, (const float4*)k_in,
                              (const float4*)v_in, (const float4*)W,
                              (uint2*)xin_hi, (uint2*)xin_lo,
                              (uint2*)w_hi, (uint2*)w_lo,
                              (int)(ND / 4), DIM * DIM / 4);
    }

    // Projections (q,k,v in one launch via z): [8192,1024] = X @ W^T + b
    {
        dim3 g(DIM / 128, (NBATCH * SEQ) / 128, 3);
        gemm_mma<1, 0><<<g, 256, SMEM_DYN>>>(xin_hi, xin_lo, w_hi, w_lo,
                                             nullptr, qkv_hi, qkv_lo, bias, 1.0f,
                                             DIM, DIM, DIM, DIM, ND, 0, ND);
    }

    const __nv_bfloat16* q_hi = qkv_hi;          const __nv_bfloat16* q_lo = qkv_lo;
    const __nv_bfloat16* k_hi = qkv_hi + ND;     const __nv_bfloat16* k_lo = qkv_lo + ND;
    const __nv_bfloat16* v_hi = qkv_hi + 2 * ND; const __nv_bfloat16* v_lo = qkv_lo + 2 * ND;

    // Scores: S[n] = (q[n] @ k[n]^T) / 32
    {
        dim3 g(SEQ / 128, SEQ / 128, NBATCH);
        gemm_mma<0, 0><<<g, 256, SMEM_DYN>>>(q_hi, q_lo, k_hi, k_lo,
                                             sbuf, nullptr, nullptr, nullptr,
                                             1.0f / 32.0f, DIM, DIM, DIM, SEQ,
                                             (long long)SEQ * DIM, (long long)SEQ * DIM,
                                             (long long)SEQ * SEQ);
    }

    // Softmax -> hi/lo probs
    softmax_rows<<<NBATCH * SEQ, 256>>>(sbuf, p_hi, p_lo);

    // PV: y[n] = P[n] @ v[n]; v row-major [t][d] consumed via ldmatrix.trans
    {
        dim3 g(DIM / 128, SEQ / 128, NBATCH);
        gemm_mma<0, 1><<<g, 256, SMEM_DYN>>>(p_hi, p_lo, v_hi, v_lo,
                                             out, nullptr, nullptr, nullptr,
                                             1.0f, SEQ, SEQ, DIM, DIM,
                                             (long long)SEQ * SEQ, (long long)SEQ * DIM,
                                             (long long)SEQ * DIM);
    }
}